// round 4
// baseline (speedup 1.0000x reference)
#include <cuda_runtime.h>
#include <cstdint>

// ---------------- configuration ----------------
#define T_STEPS   30
#define HDIM      128
#define EDIM      16
#define KDIM      144          // 128 (h) + 16 (x)
#define BTILE     64           // batch elements per CTA
#define TM        8            // batch per thread
#define TU        2            // units per thread
#define NTHREADS  512
#define KC        36           // k per staged chunk
#define NCHUNK    4            // 4*36 = 144
#define HP        68           // h_sh row pitch (floats), pad to soften STS conflicts
#define WCHUNK_FLOATS (KC*512) // 18432 floats = 72KB per chunk

// permuted concatenated weights: Wp[k][ug][j], j = u_local*4 + gate (i,f,g,o)
__device__ float g_Wp[KDIM * 512];
__device__ float g_biasp[512];     // b_ih + b_hh, same (ug,j) permutation

typedef unsigned long long u64;

__device__ __forceinline__ u64 fma2(u64 a, u64 b, u64 c) {
    u64 d;
    asm("fma.rn.f32x2 %0, %1, %2, %3;" : "=l"(d) : "l"(a), "l"(b), "l"(c));
    return d;
}
__device__ __forceinline__ u64 dup2(float x) {
    u64 d;
    asm("mov.b64 %0, {%1, %2};" : "=l"(d) : "f"(x), "f"(x));
    return d;
}
__device__ __forceinline__ void unpk(u64 v, float& lo, float& hi) {
    asm("mov.b64 {%0, %1}, %2;" : "=f"(lo), "=f"(hi) : "l"(v));
}
__device__ __forceinline__ float sigmoidf_(float x) {
    float e = __expf(-x);                  // overflow-safe: x<<0 -> e=inf -> 0
    return __fdividef(1.0f, 1.0f + e);
}
__device__ __forceinline__ float tanhf_(float x) {
    float a = fabsf(x);
    float e = __expf(-2.0f * a);           // in (0,1], no overflow
    float r = __fdividef(1.0f - e, 1.0f + e);
    return copysignf(r, x);
}
__device__ __forceinline__ void cp16(uint32_t dst, const void* src) {
    asm volatile("cp.async.cg.shared.global [%0], [%1], 16;" :: "r"(dst), "l"(src) : "memory");
}
__device__ __forceinline__ void cp_commit() { asm volatile("cp.async.commit_group;" ::: "memory"); }
__device__ __forceinline__ void cp_wait0()  { asm volatile("cp.async.wait_group 0;" ::: "memory"); }

// ---------------- weight permutation pre-pass ----------------
__global__ void prep_kernel(const float* __restrict__ W_ih, const float* __restrict__ b_ih,
                            const float* __restrict__ W_hh, const float* __restrict__ b_hh) {
    int idx = blockIdx.x * blockDim.x + threadIdx.x;
    if (idx >= KDIM * 512) return;
    int k   = idx >> 9;
    int rem = idx & 511;
    int ug = rem >> 3;
    int j  = rem & 7;
    int u  = 2 * ug + (j >> 2);
    int g  = j & 3;                 // gate order i,f,g,o (PyTorch)
    int row = g * HDIM + u;
    g_Wp[idx] = (k < HDIM) ? W_hh[row * HDIM + k] : W_ih[row * EDIM + (k - HDIM)];
    if (idx < 512) g_biasp[idx] = b_ih[row] + b_hh[row];
}

// ---------------- main persistent LSTM kernel ----------------
__device__ __forceinline__ void stage_chunk(int chunk, float* dstbuf, int tid) {
    const float4* src = (const float4*)(g_Wp + (size_t)chunk * WCHUNK_FLOATS);
    uint32_t dbase = (uint32_t)__cvta_generic_to_shared(dstbuf);
#pragma unroll
    for (int r = 0; r < 9; r++) {
        int i = tid + r * NTHREADS;   // covers 4608 float4 = 18432 floats
        cp16(dbase + i * 16, src + i);
    }
}

__global__ __launch_bounds__(NTHREADS, 1)
void lstm_kernel(const float* __restrict__ rel_in,   // last_obs_rel (B,2)
                 const float* __restrict__ h0,       // (1,B,128)
                 const float* __restrict__ c0,       // (1,B,128)
                 const float* __restrict__ W_sp,     // (16,2)
                 const float* __restrict__ b_sp,     // (16)
                 const float* __restrict__ W_out,    // (2,128)
                 const float* __restrict__ b_out,    // (2)
                 float* __restrict__ out)            // (B,30,2)
{
    extern __shared__ float smem[];
    float* wbuf0   = smem;
    float* wbuf1   = smem + WCHUNK_FLOATS;
    float* h_sh    = smem + 2 * WCHUNK_FLOATS;        // [144][HP]
    float* wout_sh = h_sh + KDIM * HP;                // 256
    float* wsp_sh  = wout_sh + 256;                   // 32
    float* bsp_sh  = wsp_sh + 32;                     // 16
    float* bout_sh = bsp_sh + 16;                     // 8 (2 used)
    float* rel_sh  = bout_sh + 8;                     // 128
    float* bias_sh = rel_sh + 128;                    // 512

    const int tid    = threadIdx.x;
    const int ug     = tid & 63;          // unit group: units 2*ug, 2*ug+1
    const int mg     = tid >> 6;          // batch group
    const int m0     = mg * TM;
    const int batch0 = blockIdx.x * BTILE;

    // small weights -> shared
    if (tid < 256) wout_sh[tid] = W_out[tid];
    if (tid < 32)  wsp_sh[tid]  = W_sp[tid];
    if (tid < 16)  bsp_sh[tid]  = b_sp[tid];
    if (tid < 2)   bout_sh[tid] = b_out[tid];
    bias_sh[tid] = g_biasp[tid];

    // h0 -> h_sh transposed: h_sh[u][m]
    {
        const float4* h4 = (const float4*)h0;
#pragma unroll
        for (int r = 0; r < 4; r++) {
            int i = tid + r * NTHREADS;            // 0..2047
            int m = i >> 5;
            int q = i & 31;
            float4 v = h4[(size_t)(batch0 + m) * 32 + q];
            h_sh[(4 * q + 0) * HP + m] = v.x;
            h_sh[(4 * q + 1) * HP + m] = v.y;
            h_sh[(4 * q + 2) * HP + m] = v.z;
            h_sh[(4 * q + 3) * HP + m] = v.w;
        }
    }
    __syncthreads();   // wsp/bsp visible before x0

    // x0 = tanh(last_obs_rel @ W_sp^T + b_sp) -> h_sh rows 128..143
#pragma unroll
    for (int r = 0; r < 2; r++) {
        int idx = tid + r * NTHREADS;              // 0..1023
        int m = idx >> 4;
        int e = idx & 15;
        float r0 = rel_in[(size_t)(batch0 + m) * 2 + 0];
        float r1 = rel_in[(size_t)(batch0 + m) * 2 + 1];
        float xv = tanhf_(fmaf(wsp_sh[e * 2 + 0], r0, fmaf(wsp_sh[e * 2 + 1], r1, bsp_sh[e])));
        h_sh[(HDIM + e) * HP + m] = xv;
    }

    // c0 -> registers (per-thread (m, u) ownership)
    float creg[TM][TU];
#pragma unroll
    for (int mi = 0; mi < TM; mi++)
#pragma unroll
        for (int ul = 0; ul < TU; ul++)
            creg[mi][ul] = c0[(size_t)(batch0 + m0 + mi) * HDIM + (2 * ug + ul)];

    // prefetch first weight chunk
    stage_chunk(0, wbuf0, tid);
    cp_commit();

    int cc = 0;  // global chunk counter
    for (int t = 0; t < T_STEPS; t++) {
        // init accumulators with fused bias (both batch lanes same bias)
        u64 acc[4][8];
        {
            float4 b0 = *(const float4*)&bias_sh[ug * 8];
            float4 b1 = *(const float4*)&bias_sh[ug * 8 + 4];
            u64 bj0 = dup2(b0.x), bj1 = dup2(b0.y), bj2 = dup2(b0.z), bj3 = dup2(b0.w);
            u64 bj4 = dup2(b1.x), bj5 = dup2(b1.y), bj6 = dup2(b1.z), bj7 = dup2(b1.w);
#pragma unroll
            for (int m2 = 0; m2 < 4; m2++) {
                acc[m2][0] = bj0; acc[m2][1] = bj1; acc[m2][2] = bj2; acc[m2][3] = bj3;
                acc[m2][4] = bj4; acc[m2][5] = bj5; acc[m2][6] = bj6; acc[m2][7] = bj7;
            }
        }

#pragma unroll 1
        for (int c = 0; c < NCHUNK; c++) {
            cp_wait0();          // chunk cc staged
            __syncthreads();     // all warps past previous chunk compute; staged data visible
            {                    // prefetch next chunk into the other buffer
                int nc = cc + 1;
                stage_chunk(nc & 3, (nc & 1) ? wbuf1 : wbuf0, tid);
                cp_commit();
            }
            const float* wb = (cc & 1) ? wbuf1 : wbuf0;
            const int kb = (cc & 3) * KC;

#pragma unroll 2
            for (int kk = 0; kk < KC; kk++) {
                const float* hrow = &h_sh[(kb + kk) * HP + m0];
                ulonglong2 hA = *(const ulonglong2*)(hrow);       // pairs (m0,m0+1),(m0+2,m0+3)
                ulonglong2 hB = *(const ulonglong2*)(hrow + 4);
                const float4* wp4 = (const float4*)&wb[(kk * 64 + ug) * 8];
                float4 w0 = wp4[0], w1 = wp4[1];
                u64 d0 = dup2(w0.x), d1 = dup2(w0.y), d2 = dup2(w0.z), d3 = dup2(w0.w);
                u64 d4 = dup2(w1.x), d5 = dup2(w1.y), d6 = dup2(w1.z), d7 = dup2(w1.w);
                u64 hp0 = hA.x, hp1 = hA.y, hp2 = hB.x, hp3 = hB.y;
#define FMAROW(M2, HP_) \
                acc[M2][0] = fma2(HP_, d0, acc[M2][0]); acc[M2][1] = fma2(HP_, d1, acc[M2][1]); \
                acc[M2][2] = fma2(HP_, d2, acc[M2][2]); acc[M2][3] = fma2(HP_, d3, acc[M2][3]); \
                acc[M2][4] = fma2(HP_, d4, acc[M2][4]); acc[M2][5] = fma2(HP_, d5, acc[M2][5]); \
                acc[M2][6] = fma2(HP_, d6, acc[M2][6]); acc[M2][7] = fma2(HP_, d7, acc[M2][7]);
                FMAROW(0, hp0)
                FMAROW(1, hp1)
                FMAROW(2, hp2)
                FMAROW(3, hp3)
#undef FMAROW
            }
            cc++;
        }

        __syncthreads();   // all GEMM reads of h_sh done before overwrite

        // activations + state update; write h_new transposed to h_sh
#pragma unroll
        for (int ul = 0; ul < TU; ul++) {
            float hn[TM];
#pragma unroll
            for (int m2 = 0; m2 < 4; m2++) {
                float zi0, zi1, zf0, zf1, zg0, zg1, zo0, zo1;
                unpk(acc[m2][ul * 4 + 0], zi0, zi1);
                unpk(acc[m2][ul * 4 + 1], zf0, zf1);
                unpk(acc[m2][ul * 4 + 2], zg0, zg1);
                unpk(acc[m2][ul * 4 + 3], zo0, zo1);
                {
                    float i_ = sigmoidf_(zi0), f_ = sigmoidf_(zf0);
                    float g_ = tanhf_(zg0),    o_ = sigmoidf_(zo0);
                    float cn = f_ * creg[2 * m2 + 0][ul] + i_ * g_;
                    creg[2 * m2 + 0][ul] = cn;
                    hn[2 * m2 + 0] = o_ * tanhf_(cn);
                }
                {
                    float i_ = sigmoidf_(zi1), f_ = sigmoidf_(zf1);
                    float g_ = tanhf_(zg1),    o_ = sigmoidf_(zo1);
                    float cn = f_ * creg[2 * m2 + 1][ul] + i_ * g_;
                    creg[2 * m2 + 1][ul] = cn;
                    hn[2 * m2 + 1] = o_ * tanhf_(cn);
                }
            }
            int u = 2 * ug + ul;
            *(float4*)&h_sh[u * HP + m0]     = make_float4(hn[0], hn[1], hn[2], hn[3]);
            *(float4*)&h_sh[u * HP + m0 + 4] = make_float4(hn[4], hn[5], hn[6], hn[7]);
        }
        __syncthreads();

        // rel_pos = h_new @ W_out^T + b_out  (128 threads: 64 m x 2 comps)
        if (tid < 128) {
            int comp = tid >> 6;
            int m    = tid & 63;
            const float* wo = &wout_sh[comp * HDIM];
            float s0 = 0.f, s1 = 0.f, s2 = 0.f, s3 = 0.f;
#pragma unroll
            for (int u = 0; u < HDIM; u += 4) {
                s0 = fmaf(h_sh[(u + 0) * HP + m], wo[u + 0], s0);
                s1 = fmaf(h_sh[(u + 1) * HP + m], wo[u + 1], s1);
                s2 = fmaf(h_sh[(u + 2) * HP + m], wo[u + 2], s2);
                s3 = fmaf(h_sh[(u + 3) * HP + m], wo[u + 3], s3);
            }
            float r = (s0 + s1) + (s2 + s3) + bout_sh[comp];
            rel_sh[m * 2 + comp] = r;
            out[(size_t)(batch0 + m) * (T_STEPS * 2) + t * 2 + comp] = r;
        }
        __syncthreads();

        // x_{t+1} = tanh(rel_pos @ W_sp^T + b_sp) -> h_sh rows 128..143
#pragma unroll
        for (int r2 = 0; r2 < 2; r2++) {
            int idx = tid + r2 * NTHREADS;
            int m = idx >> 4;
            int e = idx & 15;
            float xv = tanhf_(fmaf(wsp_sh[e * 2 + 0], rel_sh[m * 2 + 0],
                              fmaf(wsp_sh[e * 2 + 1], rel_sh[m * 2 + 1], bsp_sh[e])));
            h_sh[(HDIM + e) * HP + m] = xv;
        }
        // next chunk-top __syncthreads makes these visible before the GEMM reads
    }
}

// ---------------- launch ----------------
extern "C" void kernel_launch(void* const* d_in, const int* in_sizes, int n_in,
                              void* d_out, int out_size) {
    const float* last_obs_rel = (const float*)d_in[1];
    const float* h0    = (const float*)d_in[2];
    const float* c0    = (const float*)d_in[3];
    const float* W_sp  = (const float*)d_in[4];
    const float* b_sp  = (const float*)d_in[5];
    const float* W_ih  = (const float*)d_in[6];
    const float* b_ih  = (const float*)d_in[7];
    const float* W_hh  = (const float*)d_in[8];
    const float* b_hh  = (const float*)d_in[9];
    const float* W_out = (const float*)d_in[10];
    const float* b_out = (const float*)d_in[11];
    float* out = (float*)d_out;

    const int batch = in_sizes[2] / HDIM;          // h0 is (1, B, 128)
    const int nblocks = batch / BTILE;

    // shared: 2 W chunks + h_sh + misc
    const int smem_floats = 2 * WCHUNK_FLOATS + KDIM * HP + 256 + 32 + 16 + 8 + 128 + 512;
    const int smem_bytes = smem_floats * (int)sizeof(float);   // ~190KB
    cudaFuncSetAttribute(lstm_kernel, cudaFuncAttributeMaxDynamicSharedMemorySize, smem_bytes);

    prep_kernel<<<(KDIM * 512 + 511) / 512, 512>>>(W_ih, b_ih, W_hh, b_hh);
    lstm_kernel<<<nblocks, NTHREADS, smem_bytes>>>(last_obs_rel, h0, c0,
                                                   W_sp, b_sp, W_out, b_out, out);
}

// round 6
// speedup vs baseline: 1.0770x; 1.0770x over previous
#include <cuda_runtime.h>
#include <cstdint>

// ---------------- configuration ----------------
#define T_STEPS   30
#define HDIM      128
#define EDIM      16
#define KDIM      144          // 128 (h) + 16 (x)
#define BTILE     64           // batch elements per CTA
#define TM        8            // batch per thread
#define TU        2            // units per thread
#define NTHREADS  512
#define KC        36           // k per staged chunk
#define NCHUNK    4            // 4*36 = 144
#define HP        68           // h_sh row pitch: 272B (16B-aligned); HP ≡ 4 (mod 32 banks) -> conflict-free STS.128 at stride HP
#define WCHUNK_FLOATS (KC*512) // 18432 floats = 72KB per chunk

// plane-separated permuted weights:
//   g_Wp[((k*2 + p)*64 + ug)*4 + g]  = W[row = g*128 + (ug + 64*p)][k]
// lane (=ug) stride within a plane is 16B -> conflict-free LDS.128
__device__ float g_Wp[KDIM * 512];
__device__ float g_biasp[512];     // b_ih + b_hh, same (p,ug,g) plane layout

typedef unsigned long long u64;

__device__ __forceinline__ u64 fma2(u64 a, u64 b, u64 c) {
    u64 d;
    asm("fma.rn.f32x2 %0, %1, %2, %3;" : "=l"(d) : "l"(a), "l"(b), "l"(c));
    return d;
}
__device__ __forceinline__ u64 dup2(float x) {
    u64 d;
    asm("mov.b64 %0, {%1, %2};" : "=l"(d) : "f"(x), "f"(x));
    return d;
}
__device__ __forceinline__ void unpk(u64 v, float& lo, float& hi) {
    asm("mov.b64 {%0, %1}, %2;" : "=f"(lo), "=f"(hi) : "l"(v));
}
__device__ __forceinline__ float sigmoidf_(float x) {
    float e = __expf(-x);                  // overflow-safe: x<<0 -> e=inf -> 0
    return __fdividef(1.0f, 1.0f + e);
}
__device__ __forceinline__ float tanhf_(float x) {
    float a = fabsf(x);
    float e = __expf(-2.0f * a);           // in (0,1], no overflow
    float r = __fdividef(1.0f - e, 1.0f + e);
    return copysignf(r, x);
}
__device__ __forceinline__ void cp16(uint32_t dst, const void* src) {
    asm volatile("cp.async.cg.shared.global [%0], [%1], 16;" :: "r"(dst), "l"(src) : "memory");
}
__device__ __forceinline__ void cp_commit() { asm volatile("cp.async.commit_group;" ::: "memory"); }
__device__ __forceinline__ void cp_wait0()  { asm volatile("cp.async.wait_group 0;" ::: "memory"); }

// ---------------- weight permutation pre-pass ----------------
__global__ void prep_kernel(const float* __restrict__ W_ih, const float* __restrict__ b_ih,
                            const float* __restrict__ W_hh, const float* __restrict__ b_hh) {
    int idx = blockIdx.x * blockDim.x + threadIdx.x;
    if (idx >= KDIM * 512) return;
    int k   = idx >> 9;
    int rem = idx & 511;
    int g   = rem & 3;            // gate i,f,g,o (PyTorch order)
    int f4  = rem >> 2;           // 0..127
    int p   = f4 >> 6;            // plane
    int ug  = f4 & 63;
    int u   = ug + 64 * p;        // unit ownership: thread ug owns u=ug (plane0), u=ug+64 (plane1)
    int row = g * HDIM + u;
    g_Wp[idx] = (k < HDIM) ? W_hh[row * HDIM + k] : W_ih[row * EDIM + (k - HDIM)];
    if (idx < 512) g_biasp[idx] = b_ih[row] + b_hh[row];
}

// ---------------- main persistent LSTM kernel ----------------
__device__ __forceinline__ void stage_chunk(int chunk, float* dstbuf, int tid) {
    const float4* src = (const float4*)(g_Wp + (size_t)chunk * WCHUNK_FLOATS);
    uint32_t dbase = (uint32_t)__cvta_generic_to_shared(dstbuf);
#pragma unroll
    for (int r = 0; r < 9; r++) {
        int i = tid + r * NTHREADS;   // covers 4608 float4 = 18432 floats
        cp16(dbase + i * 16, src + i);
    }
}

__global__ __launch_bounds__(NTHREADS, 1)
void lstm_kernel(const float* __restrict__ rel_in,   // last_obs_rel (B,2)
                 const float* __restrict__ h0,       // (1,B,128)
                 const float* __restrict__ c0,       // (1,B,128)
                 const float* __restrict__ W_sp,     // (16,2)
                 const float* __restrict__ b_sp,     // (16)
                 const float* __restrict__ W_out,    // (2,128)
                 const float* __restrict__ b_out,    // (2)
                 float* __restrict__ out)            // (B,30,2)
{
    extern __shared__ float smem[];
    float* wbuf0   = smem;
    float* wbuf1   = smem + WCHUNK_FLOATS;
    float* h_sh    = smem + 2 * WCHUNK_FLOATS;        // [144][HP]
    float* wout_sh = h_sh + KDIM * HP;                // 256
    float* wsp_sh  = wout_sh + 256;                   // 32
    float* bsp_sh  = wsp_sh + 32;                     // 16
    float* bout_sh = bsp_sh + 16;                     // 8 (2 used)
    float* rel_sh  = bout_sh + 8;                     // 128
    float* bias_sh = rel_sh + 128;                    // 512 (plane layout)

    const int tid    = threadIdx.x;
    const int ug     = tid & 63;          // owns units ug and ug+64
    const int mg     = tid >> 6;          // batch group
    const int m0     = mg * TM;
    const int batch0 = blockIdx.x * BTILE;

    // small weights -> shared
    if (tid < 256) wout_sh[tid] = W_out[tid];
    if (tid < 32)  wsp_sh[tid]  = W_sp[tid];
    if (tid < 16)  bsp_sh[tid]  = b_sp[tid];
    if (tid < 2)   bout_sh[tid] = b_out[tid];
    bias_sh[tid] = g_biasp[tid];

    // h0 -> h_sh transposed: h_sh[u][m]
    {
        const float4* h4 = (const float4*)h0;
#pragma unroll
        for (int r = 0; r < 4; r++) {
            int i = tid + r * NTHREADS;            // 0..2047
            int m = i >> 5;
            int q = i & 31;
            float4 v = h4[(size_t)(batch0 + m) * 32 + q];
            h_sh[(4 * q + 0) * HP + m] = v.x;
            h_sh[(4 * q + 1) * HP + m] = v.y;
            h_sh[(4 * q + 2) * HP + m] = v.z;
            h_sh[(4 * q + 3) * HP + m] = v.w;
        }
    }
    __syncthreads();   // wsp/bsp visible before x0

    // x0 = tanh(last_obs_rel @ W_sp^T + b_sp) -> h_sh rows 128..143
#pragma unroll
    for (int r = 0; r < 2; r++) {
        int idx = tid + r * NTHREADS;              // 0..1023
        int m = idx >> 4;
        int e = idx & 15;
        float r0 = rel_in[(size_t)(batch0 + m) * 2 + 0];
        float r1 = rel_in[(size_t)(batch0 + m) * 2 + 1];
        float xv = tanhf_(fmaf(wsp_sh[e * 2 + 0], r0, fmaf(wsp_sh[e * 2 + 1], r1, bsp_sh[e])));
        h_sh[(HDIM + e) * HP + m] = xv;
    }

    // c0 -> registers (per-thread (m, u) ownership; u = ug + 64*ul)
    float creg[TM][TU];
#pragma unroll
    for (int mi = 0; mi < TM; mi++)
#pragma unroll
        for (int ul = 0; ul < TU; ul++)
            creg[mi][ul] = c0[(size_t)(batch0 + m0 + mi) * HDIM + (ug + 64 * ul)];

    // prefetch first weight chunk
    stage_chunk(0, wbuf0, tid);
    cp_commit();

    int cc = 0;  // global chunk counter
    for (int t = 0; t < T_STEPS; t++) {
        // init accumulators with fused bias (both batch lanes same bias)
        u64 acc[4][8];
        {
            float4 b0 = *(const float4*)&bias_sh[ug * 4];          // plane 0 (u=ug)
            float4 b1 = *(const float4*)&bias_sh[256 + ug * 4];    // plane 1 (u=ug+64)
            u64 bj0 = dup2(b0.x), bj1 = dup2(b0.y), bj2 = dup2(b0.z), bj3 = dup2(b0.w);
            u64 bj4 = dup2(b1.x), bj5 = dup2(b1.y), bj6 = dup2(b1.z), bj7 = dup2(b1.w);
#pragma unroll
            for (int m2 = 0; m2 < 4; m2++) {
                acc[m2][0] = bj0; acc[m2][1] = bj1; acc[m2][2] = bj2; acc[m2][3] = bj3;
                acc[m2][4] = bj4; acc[m2][5] = bj5; acc[m2][6] = bj6; acc[m2][7] = bj7;
            }
        }

#pragma unroll 1
        for (int c = 0; c < NCHUNK; c++) {
            cp_wait0();          // chunk cc staged
            __syncthreads();     // all warps past previous chunk compute; staged data visible
            {                    // prefetch next chunk into the other buffer
                int nc = cc + 1;
                stage_chunk(nc & 3, (nc & 1) ? wbuf1 : wbuf0, tid);
                cp_commit();
            }
            const float* wb = (cc & 1) ? wbuf1 : wbuf0;
            const int kb = (cc & 3) * KC;

#pragma unroll 2
            for (int kk = 0; kk < KC; kk++) {
                const float* hrow = &h_sh[(kb + kk) * HP + m0];
                ulonglong2 hA = *(const ulonglong2*)(hrow);       // pairs (m0,m0+1),(m0+2,m0+3)
                ulonglong2 hB = *(const ulonglong2*)(hrow + 4);
                // plane-separated, conflict-free weight loads (16B lane stride)
                const float4* wpA = (const float4*)wb + (kk * 128 + ug);
                float4 w0 = wpA[0];        // plane 0: gates i,f,g,o of u=ug
                float4 w1 = wpA[64];       // plane 1: gates i,f,g,o of u=ug+64
                u64 d0 = dup2(w0.x), d1 = dup2(w0.y), d2 = dup2(w0.z), d3 = dup2(w0.w);
                u64 d4 = dup2(w1.x), d5 = dup2(w1.y), d6 = dup2(w1.z), d7 = dup2(w1.w);
                u64 hp0 = hA.x, hp1 = hA.y, hp2 = hB.x, hp3 = hB.y;
#define FMAROW(M2, HP_) \
                acc[M2][0] = fma2(HP_, d0, acc[M2][0]); acc[M2][1] = fma2(HP_, d1, acc[M2][1]); \
                acc[M2][2] = fma2(HP_, d2, acc[M2][2]); acc[M2][3] = fma2(HP_, d3, acc[M2][3]); \
                acc[M2][4] = fma2(HP_, d4, acc[M2][4]); acc[M2][5] = fma2(HP_, d5, acc[M2][5]); \
                acc[M2][6] = fma2(HP_, d6, acc[M2][6]); acc[M2][7] = fma2(HP_, d7, acc[M2][7]);
                FMAROW(0, hp0)
                FMAROW(1, hp1)
                FMAROW(2, hp2)
                FMAROW(3, hp3)
#undef FMAROW
            }
            cc++;
        }

        __syncthreads();   // all GEMM reads of h_sh done before overwrite

        // activations + state update; write h_new transposed to h_sh
#pragma unroll
        for (int ul = 0; ul < TU; ul++) {
            float hn[TM];
#pragma unroll
            for (int m2 = 0; m2 < 4; m2++) {
                float zi0, zi1, zf0, zf1, zg0, zg1, zo0, zo1;
                unpk(acc[m2][ul * 4 + 0], zi0, zi1);
                unpk(acc[m2][ul * 4 + 1], zf0, zf1);
                unpk(acc[m2][ul * 4 + 2], zg0, zg1);
                unpk(acc[m2][ul * 4 + 3], zo0, zo1);
                {
                    float i_ = sigmoidf_(zi0), f_ = sigmoidf_(zf0);
                    float g_ = tanhf_(zg0),    o_ = sigmoidf_(zo0);
                    float cn = f_ * creg[2 * m2 + 0][ul] + i_ * g_;
                    creg[2 * m2 + 0][ul] = cn;
                    hn[2 * m2 + 0] = o_ * tanhf_(cn);
                }
                {
                    float i_ = sigmoidf_(zi1), f_ = sigmoidf_(zf1);
                    float g_ = tanhf_(zg1),    o_ = sigmoidf_(zo1);
                    float cn = f_ * creg[2 * m2 + 1][ul] + i_ * g_;
                    creg[2 * m2 + 1][ul] = cn;
                    hn[2 * m2 + 1] = o_ * tanhf_(cn);
                }
            }
            int u = ug + 64 * ul;      // per-lane store stride = HP floats ≡ 4 banks -> conflict-free
            *(float4*)&h_sh[u * HP + m0]     = make_float4(hn[0], hn[1], hn[2], hn[3]);
            *(float4*)&h_sh[u * HP + m0 + 4] = make_float4(hn[4], hn[5], hn[6], hn[7]);
        }
        __syncthreads();

        // rel_pos = h_new @ W_out^T + b_out  (128 threads: 64 m x 2 comps)
        if (tid < 128) {
            int comp = tid >> 6;
            int m    = tid & 63;
            const float* wo = &wout_sh[comp * HDIM];
            float s0 = 0.f, s1 = 0.f, s2 = 0.f, s3 = 0.f;
#pragma unroll
            for (int u = 0; u < HDIM; u += 4) {
                s0 = fmaf(h_sh[(u + 0) * HP + m], wo[u + 0], s0);
                s1 = fmaf(h_sh[(u + 1) * HP + m], wo[u + 1], s1);
                s2 = fmaf(h_sh[(u + 2) * HP + m], wo[u + 2], s2);
                s3 = fmaf(h_sh[(u + 3) * HP + m], wo[u + 3], s3);
            }
            float r = (s0 + s1) + (s2 + s3) + bout_sh[comp];
            rel_sh[m * 2 + comp] = r;
            out[(size_t)(batch0 + m) * (T_STEPS * 2) + t * 2 + comp] = r;
        }
        __syncthreads();

        // x_{t+1} = tanh(rel_pos @ W_sp^T + b_sp) -> h_sh rows 128..143
#pragma unroll
        for (int r2 = 0; r2 < 2; r2++) {
            int idx = tid + r2 * NTHREADS;
            int m = idx >> 4;
            int e = idx & 15;
            float xv = tanhf_(fmaf(wsp_sh[e * 2 + 0], rel_sh[m * 2 + 0],
                              fmaf(wsp_sh[e * 2 + 1], rel_sh[m * 2 + 1], bsp_sh[e])));
            h_sh[(HDIM + e) * HP + m] = xv;
        }
        // next chunk-top __syncthreads makes these visible before the GEMM reads
    }
}

// ---------------- launch ----------------
extern "C" void kernel_launch(void* const* d_in, const int* in_sizes, int n_in,
                              void* d_out, int out_size) {
    const float* last_obs_rel = (const float*)d_in[1];
    const float* h0    = (const float*)d_in[2];
    const float* c0    = (const float*)d_in[3];
    const float* W_sp  = (const float*)d_in[4];
    const float* b_sp  = (const float*)d_in[5];
    const float* W_ih  = (const float*)d_in[6];
    const float* b_ih  = (const float*)d_in[7];
    const float* W_hh  = (const float*)d_in[8];
    const float* b_hh  = (const float*)d_in[9];
    const float* W_out = (const float*)d_in[10];
    const float* b_out = (const float*)d_in[11];
    float* out = (float*)d_out;

    const int batch = in_sizes[2] / HDIM;          // h0 is (1, B, 128)
    const int nblocks = batch / BTILE;

    // shared: 2 W chunks + h_sh + misc
    const int smem_floats = 2 * WCHUNK_FLOATS + KDIM * HP + 256 + 32 + 16 + 8 + 128 + 512;
    const int smem_bytes = smem_floats * (int)sizeof(float);   // ~190KB
    cudaFuncSetAttribute(lstm_kernel, cudaFuncAttributeMaxDynamicSharedMemorySize, smem_bytes);

    prep_kernel<<<(KDIM * 512 + 511) / 512, 512>>>(W_ih, b_ih, W_hh, b_hh);
    lstm_kernel<<<nblocks, NTHREADS, smem_bytes>>>(last_obs_rel, h0, c0,
                                                   W_sp, b_sp, W_out, b_out, out);
}

// round 7
// speedup vs baseline: 1.0771x; 1.0001x over previous
#include <cuda_runtime.h>
#include <cstdint>

// ---------------- configuration ----------------
#define T_STEPS   30
#define HDIM      128
#define EDIM      16
#define KDIM      144          // 128 (h) + 16 (x)
#define BTILE     64           // batch elements per CTA
#define TM        8            // batch per thread
#define TU        2            // units per thread
#define NTHREADS  512
#define KC        36           // k per staged chunk
#define NCHUNK    4            // 4*36 = 144
#define HP        68           // h_sh row pitch: 272B (16B-aligned); HP ≡ 4 (mod 32 banks) -> conflict-free STS.128 at stride HP
#define WCHUNK_FLOATS (KC*512) // 18432 floats = 72KB per chunk

// plane-separated permuted weights:
//   g_Wp[((k*2 + p)*64 + ug)*4 + g]  = W[row = g*128 + (ug + 64*p)][k]
// lane (=ug) stride within a plane is 16B -> conflict-free LDS.128
__device__ float g_Wp[KDIM * 512];
__device__ float g_biasp[512];     // b_ih + b_hh, same (p,ug,g) plane layout

typedef unsigned long long u64;

__device__ __forceinline__ u64 fma2(u64 a, u64 b, u64 c) {
    u64 d;
    asm("fma.rn.f32x2 %0, %1, %2, %3;" : "=l"(d) : "l"(a), "l"(b), "l"(c));
    return d;
}
__device__ __forceinline__ u64 dup2(float x) {
    u64 d;
    asm("mov.b64 %0, {%1, %2};" : "=l"(d) : "f"(x), "f"(x));
    return d;
}
__device__ __forceinline__ void unpk(u64 v, float& lo, float& hi) {
    asm("mov.b64 {%0, %1}, %2;" : "=f"(lo), "=f"(hi) : "l"(v));
}
__device__ __forceinline__ float sigmoidf_(float x) {
    float e = __expf(-x);                  // overflow-safe: x<<0 -> e=inf -> 0
    return __fdividef(1.0f, 1.0f + e);
}
__device__ __forceinline__ float tanhf_(float x) {
    float a = fabsf(x);
    float e = __expf(-2.0f * a);           // in (0,1], no overflow
    float r = __fdividef(1.0f - e, 1.0f + e);
    return copysignf(r, x);
}
__device__ __forceinline__ void cp16(uint32_t dst, const void* src) {
    asm volatile("cp.async.cg.shared.global [%0], [%1], 16;" :: "r"(dst), "l"(src) : "memory");
}
__device__ __forceinline__ void cp_commit() { asm volatile("cp.async.commit_group;" ::: "memory"); }
__device__ __forceinline__ void cp_wait0()  { asm volatile("cp.async.wait_group 0;" ::: "memory"); }

// ---------------- weight permutation pre-pass ----------------
__global__ void prep_kernel(const float* __restrict__ W_ih, const float* __restrict__ b_ih,
                            const float* __restrict__ W_hh, const float* __restrict__ b_hh) {
    int idx = blockIdx.x * blockDim.x + threadIdx.x;
    if (idx >= KDIM * 512) return;
    int k   = idx >> 9;
    int rem = idx & 511;
    int g   = rem & 3;            // gate i,f,g,o (PyTorch order)
    int f4  = rem >> 2;           // 0..127
    int p   = f4 >> 6;            // plane
    int ug  = f4 & 63;
    int u   = ug + 64 * p;        // unit ownership: thread ug owns u=ug (plane0), u=ug+64 (plane1)
    int row = g * HDIM + u;
    g_Wp[idx] = (k < HDIM) ? W_hh[row * HDIM + k] : W_ih[row * EDIM + (k - HDIM)];
    if (idx < 512) g_biasp[idx] = b_ih[row] + b_hh[row];
}

// ---------------- main persistent LSTM kernel ----------------
__device__ __forceinline__ void stage_chunk(int chunk, float* dstbuf, int tid) {
    const float4* src = (const float4*)(g_Wp + (size_t)chunk * WCHUNK_FLOATS);
    uint32_t dbase = (uint32_t)__cvta_generic_to_shared(dstbuf);
#pragma unroll
    for (int r = 0; r < 9; r++) {
        int i = tid + r * NTHREADS;   // covers 4608 float4 = 18432 floats
        cp16(dbase + i * 16, src + i);
    }
}

__global__ __launch_bounds__(NTHREADS, 1)
void lstm_kernel(const float* __restrict__ rel_in,   // last_obs_rel (B,2)
                 const float* __restrict__ h0,       // (1,B,128)
                 const float* __restrict__ c0,       // (1,B,128)
                 const float* __restrict__ W_sp,     // (16,2)
                 const float* __restrict__ b_sp,     // (16)
                 const float* __restrict__ W_out,    // (2,128)
                 const float* __restrict__ b_out,    // (2)
                 float* __restrict__ out)            // (B,30,2)
{
    extern __shared__ float smem[];
    float* wbuf0   = smem;
    float* wbuf1   = smem + WCHUNK_FLOATS;
    float* h_sh    = smem + 2 * WCHUNK_FLOATS;        // [144][HP]
    float* wout_sh = h_sh + KDIM * HP;                // 256
    float* wsp_sh  = wout_sh + 256;                   // 32
    float* bsp_sh  = wsp_sh + 32;                     // 16
    float* bout_sh = bsp_sh + 16;                     // 8 (2 used)
    float* rel_sh  = bout_sh + 8;                     // 128
    float* bias_sh = rel_sh + 128;                    // 512 (plane layout)

    const int tid    = threadIdx.x;
    const int ug     = tid & 63;          // owns units ug and ug+64
    const int mg     = tid >> 6;          // batch group
    const int m0     = mg * TM;
    const int batch0 = blockIdx.x * BTILE;

    // small weights -> shared
    if (tid < 256) wout_sh[tid] = W_out[tid];
    if (tid < 32)  wsp_sh[tid]  = W_sp[tid];
    if (tid < 16)  bsp_sh[tid]  = b_sp[tid];
    if (tid < 2)   bout_sh[tid] = b_out[tid];
    bias_sh[tid] = g_biasp[tid];

    // h0 -> h_sh transposed: h_sh[u][m]
    {
        const float4* h4 = (const float4*)h0;
#pragma unroll
        for (int r = 0; r < 4; r++) {
            int i = tid + r * NTHREADS;            // 0..2047
            int m = i >> 5;
            int q = i & 31;
            float4 v = h4[(size_t)(batch0 + m) * 32 + q];
            h_sh[(4 * q + 0) * HP + m] = v.x;
            h_sh[(4 * q + 1) * HP + m] = v.y;
            h_sh[(4 * q + 2) * HP + m] = v.z;
            h_sh[(4 * q + 3) * HP + m] = v.w;
        }
    }
    __syncthreads();   // wsp/bsp visible before x0

    // x0 = tanh(last_obs_rel @ W_sp^T + b_sp) -> h_sh rows 128..143
#pragma unroll
    for (int r = 0; r < 2; r++) {
        int idx = tid + r * NTHREADS;              // 0..1023
        int m = idx >> 4;
        int e = idx & 15;
        float r0 = rel_in[(size_t)(batch0 + m) * 2 + 0];
        float r1 = rel_in[(size_t)(batch0 + m) * 2 + 1];
        float xv = tanhf_(fmaf(wsp_sh[e * 2 + 0], r0, fmaf(wsp_sh[e * 2 + 1], r1, bsp_sh[e])));
        h_sh[(HDIM + e) * HP + m] = xv;
    }

    // c0 -> registers (per-thread (m, u) ownership; u = ug + 64*ul)
    float creg[TM][TU];
#pragma unroll
    for (int mi = 0; mi < TM; mi++)
#pragma unroll
        for (int ul = 0; ul < TU; ul++)
            creg[mi][ul] = c0[(size_t)(batch0 + m0 + mi) * HDIM + (ug + 64 * ul)];

    // prefetch first weight chunk
    stage_chunk(0, wbuf0, tid);
    cp_commit();

    int cc = 0;  // global chunk counter
    for (int t = 0; t < T_STEPS; t++) {
        // init accumulators with fused bias (both batch lanes same bias)
        u64 acc[4][8];
        {
            float4 b0 = *(const float4*)&bias_sh[ug * 4];          // plane 0 (u=ug)
            float4 b1 = *(const float4*)&bias_sh[256 + ug * 4];    // plane 1 (u=ug+64)
            u64 bj0 = dup2(b0.x), bj1 = dup2(b0.y), bj2 = dup2(b0.z), bj3 = dup2(b0.w);
            u64 bj4 = dup2(b1.x), bj5 = dup2(b1.y), bj6 = dup2(b1.z), bj7 = dup2(b1.w);
#pragma unroll
            for (int m2 = 0; m2 < 4; m2++) {
                acc[m2][0] = bj0; acc[m2][1] = bj1; acc[m2][2] = bj2; acc[m2][3] = bj3;
                acc[m2][4] = bj4; acc[m2][5] = bj5; acc[m2][6] = bj6; acc[m2][7] = bj7;
            }
        }

#pragma unroll 1
        for (int c = 0; c < NCHUNK; c++) {
            cp_wait0();          // chunk cc staged
            __syncthreads();     // all warps past previous chunk compute; staged data visible
            {                    // prefetch next chunk into the other buffer
                int nc = cc + 1;
                stage_chunk(nc & 3, (nc & 1) ? wbuf1 : wbuf0, tid);
                cp_commit();
            }
            const float* wb = (cc & 1) ? wbuf1 : wbuf0;
            const int kb = (cc & 3) * KC;

#pragma unroll 2
            for (int kk = 0; kk < KC; kk++) {
                const float* hrow = &h_sh[(kb + kk) * HP + m0];
                ulonglong2 hA = *(const ulonglong2*)(hrow);       // pairs (m0,m0+1),(m0+2,m0+3)
                ulonglong2 hB = *(const ulonglong2*)(hrow + 4);
                // plane-separated, conflict-free weight loads (16B lane stride)
                const float4* wpA = (const float4*)wb + (kk * 128 + ug);
                float4 w0 = wpA[0];        // plane 0: gates i,f,g,o of u=ug
                float4 w1 = wpA[64];       // plane 1: gates i,f,g,o of u=ug+64
                u64 d0 = dup2(w0.x), d1 = dup2(w0.y), d2 = dup2(w0.z), d3 = dup2(w0.w);
                u64 d4 = dup2(w1.x), d5 = dup2(w1.y), d6 = dup2(w1.z), d7 = dup2(w1.w);
                u64 hp0 = hA.x, hp1 = hA.y, hp2 = hB.x, hp3 = hB.y;
#define FMAROW(M2, HP_) \
                acc[M2][0] = fma2(HP_, d0, acc[M2][0]); acc[M2][1] = fma2(HP_, d1, acc[M2][1]); \
                acc[M2][2] = fma2(HP_, d2, acc[M2][2]); acc[M2][3] = fma2(HP_, d3, acc[M2][3]); \
                acc[M2][4] = fma2(HP_, d4, acc[M2][4]); acc[M2][5] = fma2(HP_, d5, acc[M2][5]); \
                acc[M2][6] = fma2(HP_, d6, acc[M2][6]); acc[M2][7] = fma2(HP_, d7, acc[M2][7]);
                FMAROW(0, hp0)
                FMAROW(1, hp1)
                FMAROW(2, hp2)
                FMAROW(3, hp3)
#undef FMAROW
            }
            cc++;
        }

        __syncthreads();   // all GEMM reads of h_sh done before overwrite

        // activations + state update; write h_new transposed to h_sh
#pragma unroll
        for (int ul = 0; ul < TU; ul++) {
            float hn[TM];
#pragma unroll
            for (int m2 = 0; m2 < 4; m2++) {
                float zi0, zi1, zf0, zf1, zg0, zg1, zo0, zo1;
                unpk(acc[m2][ul * 4 + 0], zi0, zi1);
                unpk(acc[m2][ul * 4 + 1], zf0, zf1);
                unpk(acc[m2][ul * 4 + 2], zg0, zg1);
                unpk(acc[m2][ul * 4 + 3], zo0, zo1);
                {
                    float i_ = sigmoidf_(zi0), f_ = sigmoidf_(zf0);
                    float g_ = tanhf_(zg0),    o_ = sigmoidf_(zo0);
                    float cn = f_ * creg[2 * m2 + 0][ul] + i_ * g_;
                    creg[2 * m2 + 0][ul] = cn;
                    hn[2 * m2 + 0] = o_ * tanhf_(cn);
                }
                {
                    float i_ = sigmoidf_(zi1), f_ = sigmoidf_(zf1);
                    float g_ = tanhf_(zg1),    o_ = sigmoidf_(zo1);
                    float cn = f_ * creg[2 * m2 + 1][ul] + i_ * g_;
                    creg[2 * m2 + 1][ul] = cn;
                    hn[2 * m2 + 1] = o_ * tanhf_(cn);
                }
            }
            int u = ug + 64 * ul;      // per-lane store stride = HP floats ≡ 4 banks -> conflict-free
            *(float4*)&h_sh[u * HP + m0]     = make_float4(hn[0], hn[1], hn[2], hn[3]);
            *(float4*)&h_sh[u * HP + m0 + 4] = make_float4(hn[4], hn[5], hn[6], hn[7]);
        }
        __syncthreads();

        // rel_pos = h_new @ W_out^T + b_out  (128 threads: 64 m x 2 comps)
        if (tid < 128) {
            int comp = tid >> 6;
            int m    = tid & 63;
            const float* wo = &wout_sh[comp * HDIM];
            float s0 = 0.f, s1 = 0.f, s2 = 0.f, s3 = 0.f;
#pragma unroll
            for (int u = 0; u < HDIM; u += 4) {
                s0 = fmaf(h_sh[(u + 0) * HP + m], wo[u + 0], s0);
                s1 = fmaf(h_sh[(u + 1) * HP + m], wo[u + 1], s1);
                s2 = fmaf(h_sh[(u + 2) * HP + m], wo[u + 2], s2);
                s3 = fmaf(h_sh[(u + 3) * HP + m], wo[u + 3], s3);
            }
            float r = (s0 + s1) + (s2 + s3) + bout_sh[comp];
            rel_sh[m * 2 + comp] = r;
            out[(size_t)(batch0 + m) * (T_STEPS * 2) + t * 2 + comp] = r;
        }
        __syncthreads();

        // x_{t+1} = tanh(rel_pos @ W_sp^T + b_sp) -> h_sh rows 128..143
#pragma unroll
        for (int r2 = 0; r2 < 2; r2++) {
            int idx = tid + r2 * NTHREADS;
            int m = idx >> 4;
            int e = idx & 15;
            float xv = tanhf_(fmaf(wsp_sh[e * 2 + 0], rel_sh[m * 2 + 0],
                              fmaf(wsp_sh[e * 2 + 1], rel_sh[m * 2 + 1], bsp_sh[e])));
            h_sh[(HDIM + e) * HP + m] = xv;
        }
        // next chunk-top __syncthreads makes these visible before the GEMM reads
    }
}

// ---------------- launch ----------------
extern "C" void kernel_launch(void* const* d_in, const int* in_sizes, int n_in,
                              void* d_out, int out_size) {
    const float* last_obs_rel = (const float*)d_in[1];
    const float* h0    = (const float*)d_in[2];
    const float* c0    = (const float*)d_in[3];
    const float* W_sp  = (const float*)d_in[4];
    const float* b_sp  = (const float*)d_in[5];
    const float* W_ih  = (const float*)d_in[6];
    const float* b_ih  = (const float*)d_in[7];
    const float* W_hh  = (const float*)d_in[8];
    const float* b_hh  = (const float*)d_in[9];
    const float* W_out = (const float*)d_in[10];
    const float* b_out = (const float*)d_in[11];
    float* out = (float*)d_out;

    const int batch = in_sizes[2] / HDIM;          // h0 is (1, B, 128)
    const int nblocks = batch / BTILE;

    // shared: 2 W chunks + h_sh + misc
    const int smem_floats = 2 * WCHUNK_FLOATS + KDIM * HP + 256 + 32 + 16 + 8 + 128 + 512;
    const int smem_bytes = smem_floats * (int)sizeof(float);   // ~190KB
    cudaFuncSetAttribute(lstm_kernel, cudaFuncAttributeMaxDynamicSharedMemorySize, smem_bytes);

    prep_kernel<<<(KDIM * 512 + 511) / 512, 512>>>(W_ih, b_ih, W_hh, b_hh);
    lstm_kernel<<<nblocks, NTHREADS, smem_bytes>>>(last_obs_rel, h0, c0,
                                                   W_sp, b_sp, W_out, b_out, out);
}